// round 4
// baseline (speedup 1.0000x reference)
#include <cuda_runtime.h>
#include <cuda_fp16.h>
#include <cstdint>

#define TD 256
#define TILE_M 128
#define NTHREADS 256

// ---- weight image: padded row stride 528B = 16*33 (ldmatrix phase-conflict-free) ----
#define W_STRIDE  528
#define OFF_W2I   0                       // 256 rows [k] x 528B : w2 fp16 [k][n]
#define OFF_W1I   (256 * W_STRIDE)       // 16 rows  [k] x 528B : w1 fp16 [k][n] (k>=14 zero)
#define OFF_B1F   (OFF_W1I + 16 * W_STRIDE)   // 1024B fp32: b1 + 128*w1[12,:] (const folded)
#define OFF_B2V   (OFF_B1F + 1024)            // 1024B fp32: b2
#define IMG_BYTES (OFF_B2V + 1024)            // 145664, multiple of 16
#define OFF_ST    IMG_BYTES                    // stats fp16, 128 rows x 48B stride
#define ST_STRIDE 48
#define SMEM_DYN  (OFF_ST + TILE_M * ST_STRIDE)   // 151808

__device__ __align__(16) unsigned char g_img[IMG_BYTES];

// ============================ helpers ============================
__device__ __forceinline__ uint32_t smem_u32(const void* p) {
    uint32_t a;
    asm("{ .reg .u64 t; cvta.to.shared.u64 t, %1; cvt.u32.u64 %0, t; }"
        : "=r"(a) : "l"(p));
    return a;
}

#define LDSM_X4(r0, r1, r2, r3, addr) \
    asm volatile("ldmatrix.sync.aligned.m8n8.x4.shared.b16 {%0,%1,%2,%3}, [%4];" \
        : "=r"(r0), "=r"(r1), "=r"(r2), "=r"(r3) : "r"(addr))

#define LDSM_X4_T(r0, r1, r2, r3, addr) \
    asm volatile("ldmatrix.sync.aligned.m8n8.x4.trans.shared.b16 {%0,%1,%2,%3}, [%4];" \
        : "=r"(r0), "=r"(r1), "=r"(r2), "=r"(r3) : "r"(addr))

// D += A @ B : m16n8k16, fp16 in, fp32 accumulate
#define MMA16816(c, a0, a1, a2, a3, b0, b1) \
    asm volatile("mma.sync.aligned.m16n8k16.row.col.f32.f16.f16.f32 " \
        "{%0,%1,%2,%3}, {%4,%5,%6,%7}, {%8,%9}, {%0,%1,%2,%3};" \
        : "+f"((c)[0]), "+f"((c)[1]), "+f"((c)[2]), "+f"((c)[3]) \
        : "r"(a0), "r"(a1), "r"(a2), "r"(a3), "r"(b0), "r"(b1))

#define CP_ASYNC16(dst, src) \
    asm volatile("cp.async.ca.shared.global [%0], [%1], 16;" \
        :: "r"(dst), "l"(src) : "memory")

__device__ __forceinline__ float fast_gelu(float x) {
    float t = 0.7978845608f * x * fmaf(0.044715f, x * x, 1.0f);
    float th;
    asm("tanh.approx.f32 %0, %1;" : "=f"(th) : "f"(t));
    return 0.5f * x * (1.0f + th);
}

// ============================ prep kernel ============================
// Blocks 0..255: w2 row k -> fp16 image row (528B stride).
// Block 256: w1 rows (zero-padded to k=16) + folded fp32 bias + b2.
__global__ void prep_kernel(const float* __restrict__ w1, const float* __restrict__ b1,
                            const float* __restrict__ w2, const float* __restrict__ b2) {
    const int n = threadIdx.x;
    const int blk = blockIdx.x;
    if (blk < 256) {
        *(__half*)(g_img + OFF_W2I + blk * W_STRIDE + n * 2) = __float2half_rn(w2[blk * TD + n]);
    } else {
        #pragma unroll
        for (int k = 0; k < 16; k++) {
            float v = (k < 14) ? w1[k * TD + n] : 0.0f;
            *(__half*)(g_img + OFF_W1I + k * W_STRIDE + n * 2) = __float2half_rn(v);
        }
        ((float*)(g_img + OFF_B1F))[n] = b1[n] + 128.0f * w1[12 * TD + n];
        ((float*)(g_img + OFF_B2V))[n] = b2[n];
    }
}

// ============================ main fused kernel ============================
extern __shared__ char dynsmem[];

__global__ void __launch_bounds__(NTHREADS, 1)
enc_kernel(const int4* __restrict__ y4, float* __restrict__ out) {
    const int tid = threadIdx.x, wid = tid >> 5, lane = tid & 31;
    const int g = lane >> 2, tig = lane & 3;
    char* base = dynsmem;
    const uint32_t sb = smem_u32(base);
    const int tilebase = blockIdx.x * TILE_M;

    // ---- stage weight image: cp.async 16B chunks (overlaps with histogram) ----
    {
        const unsigned char* src = g_img;
        #pragma unroll 4
        for (int i = tid; i < IMG_BYTES / 16; i += NTHREADS)
            CP_ASYNC16(sb + i * 16, src + i * 16);
        asm volatile("cp.async.commit_group;" ::: "memory");
    }

    // ---- per-task histogram + stats -> fp16 rows (48B stride, ldmatrix-friendly) ----
    for (int t = wid; t < TILE_M; t += NTHREADS / 32) {
        int4 v = y4[(size_t)(tilebase + t) * 32 + lane];   // 4 labels/lane, coalesced
        int hist[10];
        #pragma unroll
        for (int c = 0; c < 10; c++) {
            int cnt = (v.x == c) + (v.y == c) + (v.z == c) + (v.w == c);
            hist[c] = __reduce_add_sync(0xffffffffu, cnt);
        }
        if (lane == 0) {
            float pv[10], ent = 0.f, pmax = 0.f;
            int nnz = 0;
            #pragma unroll
            for (int c = 0; c < 10; c++) {
                float p = (float)hist[c] * 0.0078125f;     // /128 exact; exact in fp16
                pv[c] = p;
                ent -= p * __logf(p + 1e-6f);
                nnz += (hist[c] > 0);
                pmax = fmaxf(pmax, p);
            }
            __half2* st = (__half2*)(base + OFF_ST + t * ST_STRIDE);
            st[0] = __floats2half2_rn(pv[0], pv[1]);
            st[1] = __floats2half2_rn(pv[2], pv[3]);
            st[2] = __floats2half2_rn(pv[4], pv[5]);
            st[3] = __floats2half2_rn(pv[6], pv[7]);
            st[4] = __floats2half2_rn(pv[8], pv[9]);
            st[5] = __floats2half2_rn((float)nnz, ent);
            st[6] = __floats2half2_rn(0.0f, pmax);         // k=12 zeroed (folded into bias)
            st[7] = __floats2half2_rn(0.0f, 0.0f);         // K pad 14,15
        }
    }
    asm volatile("cp.async.wait_group 0;" ::: "memory");
    __syncthreads();

    const float* b1f = (const float*)(base + OFF_B1F);
    const float* b2s = (const float*)(base + OFF_B2V);

    // ---- layer 1: h[16 rows/warp, 256] = stats @ w1 (K=16), GELU, keep as A-frags ----
    uint32_t h2[64];   // 16 k16-blocks x 4 b32 regs: A operand frags for layer 2
    {
        // A frag: stats rows m = wid*16 + (lane&15), +16B for k8..15 half
        uint32_t sa = sb + OFF_ST + (uint32_t)(wid * 16 + (lane & 15)) * ST_STRIDE
                    + ((lane & 16) ? 16u : 0u);
        uint32_t a0, a1, a2, a3;
        LDSM_X4(a0, a1, a2, a3, sa);

        const uint32_t krow = (uint32_t)(lane & 15);
        #pragma unroll
        for (int np = 0; np < 16; np++) {
            const int n0 = np * 16;
            uint32_t baddr = sb + OFF_W1I + krow * W_STRIDE
                           + ((uint32_t)n0 + ((lane & 16) ? 8u : 0u)) * 2u;
            uint32_t b0, b1_, b2_, b3;
            LDSM_X4_T(b0, b1_, b2_, b3, baddr);
            float c[8] = {0.f, 0.f, 0.f, 0.f, 0.f, 0.f, 0.f, 0.f};
            MMA16816(c + 0, a0, a1, a2, a3, b0, b1_);
            MMA16816(c + 4, a0, a1, a2, a3, b2_, b3);
            const int col0 = n0 + 2 * tig;
            float u0 = b1f[col0], u1 = b1f[col0 + 1];
            float u8 = b1f[col0 + 8], u9 = b1f[col0 + 9];
            __half2 p0 = __floats2half2_rn(fast_gelu(c[0] + u0), fast_gelu(c[1] + u1));
            __half2 p1 = __floats2half2_rn(fast_gelu(c[2] + u0), fast_gelu(c[3] + u1));
            __half2 p2 = __floats2half2_rn(fast_gelu(c[4] + u8), fast_gelu(c[5] + u9));
            __half2 p3 = __floats2half2_rn(fast_gelu(c[6] + u8), fast_gelu(c[7] + u9));
            h2[np * 4 + 0] = *(uint32_t*)&p0;   // (rows g,   k 2tig,2tig+1)
            h2[np * 4 + 1] = *(uint32_t*)&p1;   // (rows g+8)
            h2[np * 4 + 2] = *(uint32_t*)&p2;   // (rows g,   k +8)
            h2[np * 4 + 3] = *(uint32_t*)&p3;   // (rows g+8, k +8)
        }
    }

    // ---- layer 2: out[16 rows/warp, 256] = h @ w2 (K=256) + b2 ----
    {
        const int row0 = tilebase + wid * 16 + g;
        #pragma unroll 4
        for (int nt = 0; nt < 32; nt++) {
            float c[4] = {0.f, 0.f, 0.f, 0.f};
            #pragma unroll
            for (int ks = 0; ks < 8; ks++) {
                // B frags for k = ks*32 .. +31, n = nt*8 .. +7 (lanes = 32 distinct k rows)
                uint32_t baddr = sb + OFF_W2I
                               + (uint32_t)(ks * 32 + lane) * W_STRIDE + (uint32_t)nt * 16u;
                uint32_t b0, b1_, b2_, b3;
                LDSM_X4_T(b0, b1_, b2_, b3, baddr);
                MMA16816(c, h2[(2 * ks) * 4 + 0], h2[(2 * ks) * 4 + 1],
                            h2[(2 * ks) * 4 + 2], h2[(2 * ks) * 4 + 3], b0, b1_);
                MMA16816(c, h2[(2 * ks + 1) * 4 + 0], h2[(2 * ks + 1) * 4 + 1],
                            h2[(2 * ks + 1) * 4 + 2], h2[(2 * ks + 1) * 4 + 3], b2_, b3);
            }
            const int col0 = nt * 8 + 2 * tig;
            float2 v0, v1;
            v0.x = c[0] + b2s[col0];
            v0.y = c[1] + b2s[col0 + 1];
            v1.x = c[2] + b2s[col0];
            v1.y = c[3] + b2s[col0 + 1];
            *(float2*)(out + (size_t)row0 * TD + col0) = v0;
            *(float2*)(out + (size_t)(row0 + 8) * TD + col0) = v1;
        }
    }
}

// ============================ launch ============================
extern "C" void kernel_launch(void* const* d_in, const int* in_sizes, int n_in,
                              void* d_out, int out_size) {
    const int*   y  = (const int*)d_in[0];
    const float* w1 = (const float*)d_in[1];
    const float* b1 = (const float*)d_in[2];
    const float* w2 = (const float*)d_in[3];
    const float* b2 = (const float*)d_in[4];
    float* out = (float*)d_out;

    const int Btasks = in_sizes[0] / 128;          // S = 128
    const int ntiles = Btasks / TILE_M;            // 512 for B=65536

    prep_kernel<<<257, TD>>>(w1, b1, w2, b2);

    cudaFuncSetAttribute(enc_kernel, cudaFuncAttributeMaxDynamicSharedMemorySize, SMEM_DYN);
    enc_kernel<<<ntiles, NTHREADS, SMEM_DYN>>>((const int4*)y, out);
}